// round 15
// baseline (speedup 1.0000x reference)
#include <cuda_runtime.h>
#include <cstdint>

// ---------------- problem constants ----------------
#define NELEM 64
#define BMAX  16384
#define INSZ  448
#define WSZ   14336
// seg0: mi=96, mo=96, d=1 | seg1: mi=64, mo=64, d=3 | seg2: mi=32, mo=32, d=5
// g_Wt / sW transposed layout per element: [o][i], i-stride ≡4 (mod 32)
//   seg0: 96 rows stride 100 -> [0, 9600)
//   seg1: 64 rows stride  68 -> [9600, 13952)
//   seg2: 32 rows stride  36 -> [13952, 15104)
#define WT_S1 9600
#define WT_S2 13952
#define WTOT  15104
// prep transpose smem tile: [i][o], o-stride ≡1 (mod 32) -> conflict-free
#define TP_S1 9312
#define TP_S2 13472
#define TP_FLOATS 14528
#define TP_BYTES  (TP_FLOATS * 4)

#define R_ROWS 3
#define WARPS  8
#define THREADS 256
#define GRIDX 296
#define SMEM_FLOATS (WTOT + WARPS * R_ROWS * INSZ)
#define SMEM_BYTES  (SMEM_FLOATS * 4)

// ---------------- scratch (no allocation allowed) ----------------
__device__ int   g_counts[NELEM];
__device__ int   g_rows[NELEM * BMAX];   // per-element bucket regions (4 MB)
__device__ float g_Wt[NELEM * WTOT];     // pre-transposed weights (3.9 MB)

// ---------------- helpers ----------------
__device__ __forceinline__ ulonglong2 ld128(const float* p) {
    return *reinterpret_cast<const ulonglong2*>(p);
}
__device__ __forceinline__ unsigned long long ffma2(unsigned long long x,
                                                    unsigned long long w,
                                                    unsigned long long a) {
    unsigned long long d;
    asm("fma.rn.f32x2 %0, %1, %2, %3;" : "=l"(d) : "l"(x), "l"(w), "l"(a));
    return d;
}
__device__ __forceinline__ float hsum2(unsigned long long a) {
    float lo, hi;
    asm("mov.b64 {%0,%1}, %2;" : "=f"(lo), "=f"(hi) : "l"(a));
    return lo + hi;
}
__device__ __forceinline__ float4 ldcs128(const float4* p) { return __ldcs(p); }
__device__ __forceinline__ float  ldcs32(const float* p)  { return __ldcs(p); }
__device__ __forceinline__ void   stcs32(float* p, float v) { __stcs(p, v); }

// ---------------- prep: bucket build + W transpose in ONE kernel ----------
// (validated R14: rel_err 1.7e-7)
__global__ void k_prep(const int* __restrict__ idx32,
                       const float* __restrict__ W, int B) {
    extern __shared__ float ts[];
    const int tid = threadIdx.x;

    if (blockIdx.x < NELEM) {
        __shared__ int cnt;
        __shared__ int s_is64;
        const int e = blockIdx.x;
        if (tid == 0) { cnt = 0; s_is64 = 1; }
        __syncthreads();
        int bad = 0;
        for (int t = tid; t < 512; t += blockDim.x)
            if (idx32[2 * t + 1] != 0) bad = 1;
        if (bad) atomicExch(&s_is64, 0);
        __syncthreads();
        const int is64 = s_is64;

        const int lane = tid & 31;
        for (int jb = tid - lane; jb < B; jb += blockDim.x) {
            int j = jb + lane;
            int v = -1;
            if (j < B) v = is64 ? idx32[2 * j] : idx32[j];
            bool m = (v == e);
            unsigned mask = __ballot_sync(0xffffffffu, m);
            int nw = __popc(mask);
            int base = 0;
            if (lane == 0 && nw) base = atomicAdd(&cnt, nw);
            base = __shfl_sync(0xffffffffu, base, 0);
            if (m)
                g_rows[e * BMAX + base + __popc(mask & ((1u << lane) - 1u))] = j;
        }
        __syncthreads();
        if (tid == 0) g_counts[e] = cnt;
    } else {
        const int e = blockIdx.x - NELEM;
        const float* src = W + (size_t)e * WSZ;
        for (int q = tid; q < WSZ; q += blockDim.x) {
            float v = src[q];
            int a;
            if (q < 9216) {
                int i = q / 96, o = q - i * 96;
                a = i * 97 + o;
            } else if (q < 13312) {
                int r = q - 9216; int i = r >> 6, o = r & 63;
                a = TP_S1 + i * 65 + o;
            } else {
                int r = q - 13312; int i = r >> 5, o = r & 31;
                a = TP_S2 + i * 33 + o;
            }
            ts[a] = v;
        }
        __syncthreads();
        float* dst = g_Wt + (size_t)e * WTOT;
        for (int t = tid; t < WTOT; t += blockDim.x) {
            float v = 0.f;
            if (t < WT_S1) {
                int o = t / 100, i = t - o * 100;
                if (i < 96) v = ts[i * 97 + o];
            } else if (t < WT_S2) {
                int r = t - WT_S1; int o = r / 68, i = r - o * 68;
                if (i < 64) v = ts[TP_S1 + i * 65 + o];
            } else {
                int r = t - WT_S2; int o = r / 36, i = r - o * 36;
                if (i < 32) v = ts[TP_S2 + i * 33 + o];
            }
            dst[t] = v;
        }
    }
}

// ---------------- compute kernel (I$-compact version) ----------------
// R14 finding: fully-unrolled body ~32KB SASS > L1.5 I$ (32KB); 16 staggered
// warps/SM thrash I$, capping SM issue at ~29% regardless of occupancy/R/
// data-path fixes. This version rolls all i4 + staging loops (#pragma
// unroll 1) so the static body is ~5KB -> L0-resident and shared by all
// warps. r/m loops stay unrolled (register-indexed acc arrays).
__global__ __launch_bounds__(THREADS, 2)
void k_compute(const float* __restrict__ x, float* __restrict__ y) {
    extern __shared__ float sm[];
    float* sW = sm;
    const int e      = blockIdx.x & 63;
    const int chunk  = blockIdx.x >> 6;
    const int nchunk = (e < (GRIDX - NELEM * 4)) ? 5 : 4;
    const int tid  = threadIdx.x;
    const int lane = tid & 31;
    const int warp = tid >> 5;

    // W prologue: conflict-free float4 copy of pre-transposed g_Wt
    {
        const float4* ws = reinterpret_cast<const float4*>(g_Wt + (size_t)e * WTOT);
        float4* wd = reinterpret_cast<float4*>(sW);
#pragma unroll 1
        for (int t = tid; t < WTOT / 4; t += THREADS) wd[t] = ws[t];
    }
    __syncthreads();

    const int off = e * BMAX;
    const int cnt = g_counts[e];
    float* xw = sm + WTOT + warp * (R_ROWS * INSZ);

#pragma unroll 1
    for (int g = chunk * WARPS + warp; g * R_ROWS < cnt; g += nchunk * WARPS) {
        int  rows[R_ROWS];
        bool val[R_ROWS];
#pragma unroll
        for (int r = 0; r < R_ROWS; r++) {
            int li = g * R_ROWS + r;
            val[r]  = li < cnt;
            rows[r] = g_rows[off + (val[r] ? li : (cnt - 1))];
        }

        // ---- stage x rows (rolled loops; seg1/seg2 -> m-major) ----
#pragma unroll
        for (int r = 0; r < R_ROWS; r++) {
            const float* xg = x + (size_t)rows[r] * INSZ;
            float* xs = xw + r * INSZ;
            if (lane < 24)
                reinterpret_cast<float4*>(xs)[lane] =
                    ldcs128(reinterpret_cast<const float4*>(xg) + lane); // seg0
#pragma unroll 1
            for (int u = 0; u < 6; u++) {                        // seg1: 192
                int t = lane + u * 32;
                int i = t / 3, m = t - 3 * i;
                xs[96 + m * 64 + i] = ldcs32(xg + 96 + t);
            }
#pragma unroll 1
            for (int u = 0; u < 5; u++) {                        // seg2: 160
                int t = lane + u * 32;
                int i = t / 5, m = t - 5 * i;
                xs[288 + m * 32 + i] = ldcs32(xg + 288 + t);
            }
        }
        __syncwarp();

        // ================= seg0: mi=96, mo=96, d=1 =================
        {
            unsigned long long acc[3][R_ROWS];
#pragma unroll
            for (int s = 0; s < 3; s++)
#pragma unroll
                for (int r = 0; r < R_ROWS; r++) acc[s][r] = 0ull;
            const float* w0 = sW + lane * 100;
            const float* w1 = sW + (lane + 32) * 100;
            const float* w2 = sW + (lane + 64) * 100;
#pragma unroll 1
            for (int i4 = 0; i4 < 24; i4++) {
                ulonglong2 a = ld128(w0 + 4 * i4);
                ulonglong2 b = ld128(w1 + 4 * i4);
                ulonglong2 c = ld128(w2 + 4 * i4);
#pragma unroll
                for (int r = 0; r < R_ROWS; r++) {
                    ulonglong2 xv = ld128(xw + r * INSZ + 4 * i4);
                    acc[0][r] = ffma2(xv.x, a.x, acc[0][r]);
                    acc[0][r] = ffma2(xv.y, a.y, acc[0][r]);
                    acc[1][r] = ffma2(xv.x, b.x, acc[1][r]);
                    acc[1][r] = ffma2(xv.y, b.y, acc[1][r]);
                    acc[2][r] = ffma2(xv.x, c.x, acc[2][r]);
                    acc[2][r] = ffma2(xv.y, c.y, acc[2][r]);
                }
            }
#pragma unroll
            for (int r = 0; r < R_ROWS; r++) {
                if (!val[r]) continue;
                float* yg = y + (size_t)rows[r] * INSZ;
                stcs32(yg + lane,      hsum2(acc[0][r]));
                stcs32(yg + lane + 32, hsum2(acc[1][r]));
                stcs32(yg + lane + 64, hsum2(acc[2][r]));
            }
        }

        // ================= seg1: mi=64, mo=64, d=3 =================
        {
            unsigned long long acc[2][3][R_ROWS];
#pragma unroll
            for (int s = 0; s < 2; s++)
#pragma unroll
                for (int m = 0; m < 3; m++)
#pragma unroll
                    for (int r = 0; r < R_ROWS; r++) acc[s][m][r] = 0ull;
            const float* wa = sW + WT_S1 + lane * 68;
            const float* wb = sW + WT_S1 + (lane + 32) * 68;
#pragma unroll 1
            for (int i4 = 0; i4 < 16; i4++) {
                ulonglong2 a = ld128(wa + 4 * i4);
                ulonglong2 b = ld128(wb + 4 * i4);
#pragma unroll
                for (int r = 0; r < R_ROWS; r++) {
#pragma unroll
                    for (int m = 0; m < 3; m++) {
                        ulonglong2 xv =
                            ld128(xw + r * INSZ + 96 + m * 64 + 4 * i4);
                        acc[0][m][r] = ffma2(xv.x, a.x, acc[0][m][r]);
                        acc[0][m][r] = ffma2(xv.y, a.y, acc[0][m][r]);
                        acc[1][m][r] = ffma2(xv.x, b.x, acc[1][m][r]);
                        acc[1][m][r] = ffma2(xv.y, b.y, acc[1][m][r]);
                    }
                }
            }
#pragma unroll
            for (int r = 0; r < R_ROWS; r++) {
                if (!val[r]) continue;
                float* yg = y + (size_t)rows[r] * INSZ;
#pragma unroll
                for (int m = 0; m < 3; m++) {
                    stcs32(yg + 96 + lane * 3 + m,        hsum2(acc[0][m][r]));
                    stcs32(yg + 96 + (lane + 32) * 3 + m, hsum2(acc[1][m][r]));
                }
            }
        }

        // ================= seg2: mi=32, mo=32, d=5 =================
        {
            unsigned long long acc[5][R_ROWS];
#pragma unroll
            for (int m = 0; m < 5; m++)
#pragma unroll
                for (int r = 0; r < R_ROWS; r++) acc[m][r] = 0ull;
            const float* wc = sW + WT_S2 + lane * 36;
#pragma unroll 1
            for (int i4 = 0; i4 < 8; i4++) {
                ulonglong2 a = ld128(wc + 4 * i4);
#pragma unroll
                for (int r = 0; r < R_ROWS; r++) {
#pragma unroll
                    for (int m = 0; m < 5; m++) {
                        ulonglong2 xv =
                            ld128(xw + r * INSZ + 288 + m * 32 + 4 * i4);
                        acc[m][r] = ffma2(xv.x, a.x, acc[m][r]);
                        acc[m][r] = ffma2(xv.y, a.y, acc[m][r]);
                    }
                }
            }
#pragma unroll
            for (int r = 0; r < R_ROWS; r++) {
                if (!val[r]) continue;
                float* yg = y + (size_t)rows[r] * INSZ;
#pragma unroll
                for (int m = 0; m < 5; m++)
                    stcs32(yg + 288 + lane * 5 + m, hsum2(acc[m][r]));
            }
        }
        __syncwarp();  // protect xw before next group's restage
    }
}

// ---------------- launch (2 kernels total) ----------------
extern "C" void kernel_launch(void* const* d_in, const int* in_sizes, int n_in,
                              void* d_out, int out_size) {
    const float* W     = (const float*)d_in[0];
    const float* x     = (const float*)d_in[1];
    const int*   idx32 = (const int*)d_in[2];   // int32 OR int64 (auto-detected)
    float*       y     = (float*)d_out;
    const int B = in_sizes[1] / INSZ;

    cudaFuncSetAttribute(k_prep, cudaFuncAttributeMaxDynamicSharedMemorySize,
                         TP_BYTES);
    cudaFuncSetAttribute(k_compute, cudaFuncAttributeMaxDynamicSharedMemorySize,
                         SMEM_BYTES);

    k_prep<<<2 * NELEM, 512, TP_BYTES>>>(idx32, W, B);
    k_compute<<<GRIDX, THREADS, SMEM_BYTES>>>(x, y);
}

// round 17
// speedup vs baseline: 1.2449x; 1.2449x over previous
#include <cuda_runtime.h>
#include <cstdint>

// ---------------- problem constants ----------------
#define NELEM 64
#define BMAX  16384
#define INSZ  448
#define WSZ   14336
// seg0: mi=96, mo=96, d=1 | seg1: mi=64, mo=64, d=3 | seg2: mi=32, mo=32, d=5
// g_Wt / sW transposed layout per element: [o][i], i-stride ≡4 (mod 32)
//   seg0: 96 rows stride 100 -> [0, 9600)
//   seg1: 64 rows stride  68 -> [9600, 13952)
//   seg2: 32 rows stride  36 -> [13952, 15104)
#define WT_S1 9600
#define WT_S2 13952
#define WTOT  15104
// prep transpose smem tile: [i][o], o-stride ≡1 (mod 32) -> conflict-free
#define TP_S1 9312
#define TP_S2 13472
#define TP_FLOATS 14528
#define TP_BYTES  (TP_FLOATS * 4)

// R15 model (fits all rounds): ~4 cyc per memory INSTRUCTION per SM.
// R=6 minimizes mem-instr/row (W-LDS amortized over 6 rows): R10's mainloop
// (~42us) + R14's conflict-free prologue, unrolled (R15: rolling hurts).
#define R_ROWS 6
#define WARPS  4
#define THREADS 128
#define GRIDX 296
#define SMEM_FLOATS (WTOT + WARPS * R_ROWS * INSZ)
#define SMEM_BYTES  (SMEM_FLOATS * 4)

// ---------------- scratch (no allocation allowed) ----------------
__device__ int   g_counts[NELEM];
__device__ int   g_rows[NELEM * BMAX];   // per-element bucket regions (4 MB)
__device__ float g_Wt[NELEM * WTOT];     // pre-transposed weights (3.9 MB)

// ---------------- helpers ----------------
__device__ __forceinline__ ulonglong2 ld128(const float* p) {
    return *reinterpret_cast<const ulonglong2*>(p);
}
__device__ __forceinline__ unsigned long long ffma2(unsigned long long x,
                                                    unsigned long long w,
                                                    unsigned long long a) {
    unsigned long long d;
    asm("fma.rn.f32x2 %0, %1, %2, %3;" : "=l"(d) : "l"(x), "l"(w), "l"(a));
    return d;
}
__device__ __forceinline__ float hsum2(unsigned long long a) {
    float lo, hi;
    asm("mov.b64 {%0,%1}, %2;" : "=f"(lo), "=f"(hi) : "l"(a));
    return lo + hi;
}
__device__ __forceinline__ float4 ldcs128(const float4* p) { return __ldcs(p); }
__device__ __forceinline__ float  ldcs32(const float* p)  { return __ldcs(p); }
__device__ __forceinline__ void   stcs32(float* p, float v) { __stcs(p, v); }

// ---------------- prep: bucket build + W transpose in ONE kernel ----------
// (validated R14/R15: rel_err 1.7e-7)
__global__ void k_prep(const int* __restrict__ idx32,
                       const float* __restrict__ W, int B) {
    extern __shared__ float ts[];
    const int tid = threadIdx.x;

    if (blockIdx.x < NELEM) {
        __shared__ int cnt;
        __shared__ int s_is64;
        const int e = blockIdx.x;
        if (tid == 0) { cnt = 0; s_is64 = 1; }
        __syncthreads();
        int bad = 0;
        for (int t = tid; t < 512; t += blockDim.x)
            if (idx32[2 * t + 1] != 0) bad = 1;
        if (bad) atomicExch(&s_is64, 0);
        __syncthreads();
        const int is64 = s_is64;

        const int lane = tid & 31;
        for (int jb = tid - lane; jb < B; jb += blockDim.x) {
            int j = jb + lane;
            int v = -1;
            if (j < B) v = is64 ? idx32[2 * j] : idx32[j];
            bool m = (v == e);
            unsigned mask = __ballot_sync(0xffffffffu, m);
            int nw = __popc(mask);
            int base = 0;
            if (lane == 0 && nw) base = atomicAdd(&cnt, nw);
            base = __shfl_sync(0xffffffffu, base, 0);
            if (m)
                g_rows[e * BMAX + base + __popc(mask & ((1u << lane) - 1u))] = j;
        }
        __syncthreads();
        if (tid == 0) g_counts[e] = cnt;
    } else {
        const int e = blockIdx.x - NELEM;
        const float* src = W + (size_t)e * WSZ;
        for (int q = tid; q < WSZ; q += blockDim.x) {
            float v = src[q];
            int a;
            if (q < 9216) {
                int i = q / 96, o = q - i * 96;
                a = i * 97 + o;
            } else if (q < 13312) {
                int r = q - 9216; int i = r >> 6, o = r & 63;
                a = TP_S1 + i * 65 + o;
            } else {
                int r = q - 13312; int i = r >> 5, o = r & 31;
                a = TP_S2 + i * 33 + o;
            }
            ts[a] = v;
        }
        __syncthreads();
        float* dst = g_Wt + (size_t)e * WTOT;
        for (int t = tid; t < WTOT; t += blockDim.x) {
            float v = 0.f;
            if (t < WT_S1) {
                int o = t / 100, i = t - o * 100;
                if (i < 96) v = ts[i * 97 + o];
            } else if (t < WT_S2) {
                int r = t - WT_S1; int o = r / 68, i = r - o * 68;
                if (i < 64) v = ts[TP_S1 + i * 65 + o];
            } else {
                int r = t - WT_S2; int o = r / 36, i = r - o * 36;
                if (i < 32) v = ts[TP_S2 + i * 33 + o];
            }
            dst[t] = v;
        }
    }
}

// ---------------- compute kernel ----------------
// 296 CTAs, 128 threads, 2 CTAs/SM. Clean prologue (float4 copy of g_Wt),
// R=6 rows/warp-group (fewest mem-instr/row), fully unrolled f32x2 mainloop.
__global__ __launch_bounds__(THREADS, 2)
void k_compute(const float* __restrict__ x, float* __restrict__ y) {
    extern __shared__ float sm[];
    float* sW = sm;
    const int e      = blockIdx.x & 63;
    const int chunk  = blockIdx.x >> 6;
    const int nchunk = (e < (GRIDX - NELEM * 4)) ? 5 : 4;
    const int tid  = threadIdx.x;
    const int lane = tid & 31;
    const int warp = tid >> 5;

    // ---- W prologue: straight float4 copy (conflict-free) ----
    {
        const float4* ws = reinterpret_cast<const float4*>(g_Wt + (size_t)e * WTOT);
        float4* wd = reinterpret_cast<float4*>(sW);
        for (int t = tid; t < WTOT / 4; t += THREADS) wd[t] = ws[t];
    }
    __syncthreads();

    const int off = e * BMAX;
    const int cnt = g_counts[e];
    float* xw = sm + WTOT + warp * (R_ROWS * INSZ);

    for (int g = chunk * WARPS + warp; g * R_ROWS < cnt; g += nchunk * WARPS) {
        int  rows[R_ROWS];
        bool val[R_ROWS];
#pragma unroll
        for (int r = 0; r < R_ROWS; r++) {
            int li = g * R_ROWS + r;
            val[r]  = li < cnt;
            rows[r] = g_rows[off + (val[r] ? li : (cnt - 1))];
        }

        // ---- stage x rows into SMEM (seg1/seg2 transposed to m-major) ----
#pragma unroll
        for (int r = 0; r < R_ROWS; r++) {
            const float* xg = x + (size_t)rows[r] * INSZ;
            float* xs = xw + r * INSZ;
            if (lane < 24)
                reinterpret_cast<float4*>(xs)[lane] =
                    ldcs128(reinterpret_cast<const float4*>(xg) + lane); // seg0
#pragma unroll
            for (int u = 0; u < 6; u++) {                        // seg1: 192
                int t = lane + u * 32;
                int i = t / 3, m = t - 3 * i;
                xs[96 + m * 64 + i] = ldcs32(xg + 96 + t);
            }
#pragma unroll
            for (int u = 0; u < 5; u++) {                        // seg2: 160
                int t = lane + u * 32;
                int i = t / 5, m = t - 5 * i;
                xs[288 + m * 32 + i] = ldcs32(xg + 288 + t);
            }
        }
        __syncwarp();

        // ================= seg0: mi=96, mo=96, d=1 =================
        {
            unsigned long long acc[3][R_ROWS];
#pragma unroll
            for (int s = 0; s < 3; s++)
#pragma unroll
                for (int r = 0; r < R_ROWS; r++) acc[s][r] = 0ull;
            const float* w0 = sW + lane * 100;
            const float* w1 = sW + (lane + 32) * 100;
            const float* w2 = sW + (lane + 64) * 100;
#pragma unroll 4
            for (int i4 = 0; i4 < 24; i4++) {
                ulonglong2 a = ld128(w0 + 4 * i4);
                ulonglong2 b = ld128(w1 + 4 * i4);
                ulonglong2 c = ld128(w2 + 4 * i4);
#pragma unroll
                for (int r = 0; r < R_ROWS; r++) {
                    ulonglong2 xv = ld128(xw + r * INSZ + 4 * i4);
                    acc[0][r] = ffma2(xv.x, a.x, acc[0][r]);
                    acc[0][r] = ffma2(xv.y, a.y, acc[0][r]);
                    acc[1][r] = ffma2(xv.x, b.x, acc[1][r]);
                    acc[1][r] = ffma2(xv.y, b.y, acc[1][r]);
                    acc[2][r] = ffma2(xv.x, c.x, acc[2][r]);
                    acc[2][r] = ffma2(xv.y, c.y, acc[2][r]);
                }
            }
#pragma unroll
            for (int r = 0; r < R_ROWS; r++) {
                if (!val[r]) continue;
                float* yg = y + (size_t)rows[r] * INSZ;
                stcs32(yg + lane,      hsum2(acc[0][r]));
                stcs32(yg + lane + 32, hsum2(acc[1][r]));
                stcs32(yg + lane + 64, hsum2(acc[2][r]));
            }
        }

        // ================= seg1: mi=64, mo=64, d=3 =================
        {
            unsigned long long acc[2][3][R_ROWS];
#pragma unroll
            for (int s = 0; s < 2; s++)
#pragma unroll
                for (int m = 0; m < 3; m++)
#pragma unroll
                    for (int r = 0; r < R_ROWS; r++) acc[s][m][r] = 0ull;
            const float* wa = sW + WT_S1 + lane * 68;
            const float* wb = sW + WT_S1 + (lane + 32) * 68;
#pragma unroll 4
            for (int i4 = 0; i4 < 16; i4++) {
                ulonglong2 a = ld128(wa + 4 * i4);
                ulonglong2 b = ld128(wb + 4 * i4);
#pragma unroll
                for (int r = 0; r < R_ROWS; r++) {
#pragma unroll
                    for (int m = 0; m < 3; m++) {
                        ulonglong2 xv =
                            ld128(xw + r * INSZ + 96 + m * 64 + 4 * i4);
                        acc[0][m][r] = ffma2(xv.x, a.x, acc[0][m][r]);
                        acc[0][m][r] = ffma2(xv.y, a.y, acc[0][m][r]);
                        acc[1][m][r] = ffma2(xv.x, b.x, acc[1][m][r]);
                        acc[1][m][r] = ffma2(xv.y, b.y, acc[1][m][r]);
                    }
                }
            }
#pragma unroll
            for (int r = 0; r < R_ROWS; r++) {
                if (!val[r]) continue;
                float* yg = y + (size_t)rows[r] * INSZ;
#pragma unroll
                for (int m = 0; m < 3; m++) {
                    stcs32(yg + 96 + lane * 3 + m,        hsum2(acc[0][m][r]));
                    stcs32(yg + 96 + (lane + 32) * 3 + m, hsum2(acc[1][m][r]));
                }
            }
        }

        // ================= seg2: mi=32, mo=32, d=5 =================
        {
            unsigned long long acc[5][R_ROWS];
#pragma unroll
            for (int m = 0; m < 5; m++)
#pragma unroll
                for (int r = 0; r < R_ROWS; r++) acc[m][r] = 0ull;
            const float* wc = sW + WT_S2 + lane * 36;
#pragma unroll 4
            for (int i4 = 0; i4 < 8; i4++) {
                ulonglong2 a = ld128(wc + 4 * i4);
#pragma unroll
                for (int r = 0; r < R_ROWS; r++) {
#pragma unroll
                    for (int m = 0; m < 5; m++) {
                        ulonglong2 xv =
                            ld128(xw + r * INSZ + 288 + m * 32 + 4 * i4);
                        acc[m][r] = ffma2(xv.x, a.x, acc[m][r]);
                        acc[m][r] = ffma2(xv.y, a.y, acc[m][r]);
                    }
                }
            }
#pragma unroll
            for (int r = 0; r < R_ROWS; r++) {
                if (!val[r]) continue;
                float* yg = y + (size_t)rows[r] * INSZ;
#pragma unroll
                for (int m = 0; m < 5; m++)
                    stcs32(yg + 288 + lane * 5 + m, hsum2(acc[m][r]));
            }
        }
        __syncwarp();  // protect xw before next group's restage
    }
}

// ---------------- launch (2 kernels total) ----------------
extern "C" void kernel_launch(void* const* d_in, const int* in_sizes, int n_in,
                              void* d_out, int out_size) {
    const float* W     = (const float*)d_in[0];
    const float* x     = (const float*)d_in[1];
    const int*   idx32 = (const int*)d_in[2];   // int32 OR int64 (auto-detected)
    float*       y     = (float*)d_out;
    const int B = in_sizes[1] / INSZ;

    cudaFuncSetAttribute(k_prep, cudaFuncAttributeMaxDynamicSharedMemorySize,
                         TP_BYTES);
    cudaFuncSetAttribute(k_compute, cudaFuncAttributeMaxDynamicSharedMemorySize,
                         SMEM_BYTES);

    k_prep<<<2 * NELEM, 512, TP_BYTES>>>(idx32, W, B);
    k_compute<<<GRIDX, THREADS, SMEM_BYTES>>>(x, y);
}